// round 17
// baseline (speedup 1.0000x reference)
#include <cuda_runtime.h>
#include <cuda_fp16.h>
#include <cstdint>

#define EMB      64
#define CODES    16384
#define NT       1024
#define QB       128
#define NTHREADS 256
#define NSUB     32          // 32 subtiles of 32 tokens
#define NSTG     16          // subtiles per group

// per 32-token subtile: [split2][ks4][pair2][lane32][uint4] = 8192 B
#define SUB_BYTES  8192
#define SUB_FLOATS (SUB_BYTES / 4)
__device__ float g_B[NSUB][SUB_FLOATS];
__device__ float g_hE2[NT];

#define PACKH(d, lo, hi) \
    asm("cvt.rn.f16x2.f32 %0, %1, %2;" : "=r"(d) : "f"(hi), "f"(lo))

__device__ __forceinline__ float f16_rt(float v) {
    float r;
    asm("{ .reg .f16 t; cvt.rn.f16.f32 t, %1; cvt.f32.f16 %0, t; }" : "=f"(r) : "f"(v));
    return r;
}
__device__ __forceinline__ float lo_res(float v) { return v - f16_rt(v); }

__device__ __forceinline__ void mma_f16(float* d, uint4 a, uint2 b) {
    asm volatile(
        "mma.sync.aligned.m16n8k16.row.col.f32.f16.f16.f32 "
        "{%0,%1,%2,%3},{%4,%5,%6,%7},{%8,%9},{%0,%1,%2,%3};"
        : "+f"(d[0]), "+f"(d[1]), "+f"(d[2]), "+f"(d[3])
        : "r"(a.x), "r"(a.y), "r"(a.z), "r"(a.w), "r"(b.x), "r"(b.y));
}

#define CP_ASYNC16(dst, src) \
    asm volatile("cp.async.cg.shared.global [%0], [%1], 16;" :: "r"(dst), "l"(src))
#define CP_COMMIT()  asm volatile("cp.async.commit_group;" ::: "memory")
#define CP_WAIT(n)   asm volatile("cp.async.wait_group %0;" :: "n"(n) : "memory")
#define BARG(id)     asm volatile("bar.sync %0, 128;" :: "r"(id) : "memory")
#define LDS128(v, addr) \
    asm volatile("ld.shared.v4.b32 {%0,%1,%2,%3}, [%4];" \
        : "=r"((v).x), "=r"((v).y), "=r"((v).z), "=r"((v).w) : "r"(addr))
#define LDS64F(x, y, addr) \
    asm volatile("ld.shared.v2.f32 {%0,%1}, [%2];" : "=f"(x), "=f"(y) : "r"(addr))

__device__ __forceinline__ uint32_t smem_u32(const void* p) {
    uint32_t a;
    asm("{ .reg .u64 t; cvta.to.shared.u64 t, %1; cvt.u32.u64 %0, t; }" : "=r"(a) : "l"(p));
    return a;
}

// ---------------- pre-kernel: fp16 hi/lo splits of E (32-token subtiles) + halfE2 ----------------
__global__ void pre_kernel(const float* __restrict__ e) {
    const int sub = blockIdx.x;          // 0..31
    const int tid = threadIdx.x;
    char* base = (char*)&g_B[sub][0];

    {
        int lane = tid & 31;
        int pr   = (tid >> 5) & 1;
        int ks   = tid >> 6;             // 0..3
        int c = lane & 3, nq = lane >> 2;
        int k0 = ks * 16 + 2 * c;
        uint32_t hi[4], lo[4];
#pragma unroll
        for (int s = 0; s < 2; s++) {
            int tok = sub * 32 + (pr * 2 + s) * 8 + nq;
            const float* row = e + (size_t)tok * EMB;
            float v0 = row[k0], v1 = row[k0 + 1], v2 = row[k0 + 8], v3 = row[k0 + 9];
            PACKH(hi[s * 2 + 0], v0, v1);
            PACKH(hi[s * 2 + 1], v2, v3);
            PACKH(lo[s * 2 + 0], lo_res(v0), lo_res(v1));
            PACKH(lo[s * 2 + 1], lo_res(v2), lo_res(v3));
        }
        int off = ks * 1024 + pr * 512 + lane * 16;
        *(uint4*)(base + off)        = make_uint4(hi[0], hi[1], hi[2], hi[3]);
        *(uint4*)(base + 4096 + off) = make_uint4(lo[0], lo[1], lo[2], lo[3]);
    }

    if (tid < 32) {
        int tok = sub * 32 + tid;
        const float* row = e + (size_t)tok * EMB;
        float h = 0.f;
#pragma unroll
        for (int kk = 0; kk < EMB; kk++) h += row[kk] * row[kk];
        g_hE2[tok] = 0.5f * h;
    }
}

// ---------------- SMEM layout (bytes) ----------------
#define SM_A     0                        // 32768
#define SM_ST    32768                    // 4 stage buffers * 8192 = 32768
#define SM_HE2   65536                    // 4096
#define SM_REDS  69632                    // 128*2 floats
#define SM_REDI  70656
#define SM_QIDX  71680
#define SM_TOTAL 72192                    // 70.5 KB

#define LOAD_B0(B0, ksn) \
    LDS128(B0[0], bpair + (ksn) * 1024u); \
    LDS128(B0[1], bpair + (ksn) * 1024u + 512u)

#define LOAD_B1(B1, ksn) \
    LDS128(B1[0], bpair + 4096u + (ksn) * 1024u); \
    LDS128(B1[1], bpair + 4096u + (ksn) * 1024u + 512u)

#define PASSX(Am0, Am1, B) do { \
    uint2 _b; \
    _b = make_uint2(B[0].x, B[0].y); mma_f16(&acc[0],  Am0, _b); mma_f16(&acc[16], Am1, _b); \
    _b = make_uint2(B[0].z, B[0].w); mma_f16(&acc[4],  Am0, _b); mma_f16(&acc[20], Am1, _b); \
    _b = make_uint2(B[1].x, B[1].y); mma_f16(&acc[8],  Am0, _b); mma_f16(&acc[24], Am1, _b); \
    _b = make_uint2(B[1].z, B[1].w); mma_f16(&acc[12], Am0, _b); mma_f16(&acc[28], Am1, _b); \
} while (0)

// 3 products: X0E0, X1E0, X0E1 (A fragments live in registers)
#define STEP(KSN) do { \
    uint4 B0[2], B1[2]; \
    LOAD_B0(B0, KSN); \
    PASSX(A00[KSN], A01[KSN], B0); \
    LOAD_B1(B1, KSN); \
    PASSX(A10[KSN], A11[KSN], B0); \
    PASSX(A00[KSN], A01[KSN], B1); \
} while (0)

__global__ __launch_bounds__(NTHREADS, 2) void vq_kernel(
    const float* __restrict__ x,      // [B, EMB, CODES]
    const float* __restrict__ e,      // [NT, EMB]
    float* __restrict__ xout,
    float* __restrict__ idxout)
{
    extern __shared__ uint8_t sm[];
    const uint32_t smb = smem_u32(sm);
    const int tid  = threadIdx.x;
    const int warp = tid >> 5;
    const int lane = tid & 31;
    const int grp  = warp >> 2;       // 0: tokens 0-511, 1: 512-1023
    const int mw   = warp & 3;        // rows mw*32 .. +31
    const int gtid = tid & 127;
    const int b    = blockIdx.y;
    const int c0   = blockIdx.x * QB;

    const uint32_t st_base = smb + SM_ST + (uint32_t)grp * 2u * SUB_BYTES;

    // ---- cp.async prologue: subtiles grp*16, grp*16+1 ----
#pragma unroll
    for (int st = 0; st < 2; st++) {
        const char* src = (const char*)&g_B[grp * NSTG + st][0];
        uint32_t dst = st_base + st * SUB_BYTES;
#pragma unroll
        for (int it = 0; it < 4; it++) {
            int off = it * 128 * 16 + gtid * 16;
            CP_ASYNC16(dst + off, src + off);
        }
        CP_COMMIT();
    }

    // ---- pack A fragments to smem: fp16 hi/lo of x[b][k][c0+r] ----
    const float* xb = x + (size_t)b * EMB * CODES + c0;
    for (int p = tid; p < 1024; p += NTHREADS) {
        int ln = p & 31;
        int ks = (p >> 5) & 3;
        int ms = (p >> 7) & 1;
        int w  = p >> 8;
        int r  = w * 32 + ms * 16 + (ln >> 2);
        int c  = ln & 3;
        int k0 = ks * 16 + 2 * c;
        float v00 = xb[(size_t)k0 * CODES + r];
        float v01 = xb[(size_t)(k0 + 1) * CODES + r];
        float v02 = xb[(size_t)(k0 + 8) * CODES + r];
        float v03 = xb[(size_t)(k0 + 9) * CODES + r];
        float v10 = xb[(size_t)k0 * CODES + r + 8];
        float v11 = xb[(size_t)(k0 + 1) * CODES + r + 8];
        float v12 = xb[(size_t)(k0 + 8) * CODES + r + 8];
        float v13 = xb[(size_t)(k0 + 9) * CODES + r + 8];
        uint32_t a0, a1, a2, a3, l0, l1, l2, l3;
        PACKH(a0, v00, v01); PACKH(a1, v10, v11);
        PACKH(a2, v02, v03); PACKH(a3, v12, v13);
        PACKH(l0, lo_res(v00), lo_res(v01)); PACKH(l1, lo_res(v10), lo_res(v11));
        PACKH(l2, lo_res(v02), lo_res(v03)); PACKH(l3, lo_res(v12), lo_res(v13));
        int off = w * 4096 + ms * 2048 + ks * 512 + ln * 16;
        *(uint4*)(sm + SM_A + off)          = make_uint4(a0, a1, a2, a3);
        *(uint4*)(sm + SM_A + 16384 + off)  = make_uint4(l0, l1, l2, l3);
    }
    float* hE2s = (float*)(sm + SM_HE2);
    for (int i = tid; i < NT; i += NTHREADS) hE2s[i] = g_hE2[i];
    __syncthreads();

    // ---- hoist ALL A fragments into registers (invariant across subtiles) ----
    const uint32_t a0base = smb + SM_A + (uint32_t)mw * 4096u + (uint32_t)lane * 16u;
    const uint32_t a1base = a0base + 16384u;
    uint4 A00[4], A01[4], A10[4], A11[4];   // [split][m-half], per ks
#pragma unroll
    for (int ks = 0; ks < 4; ks++) {
        LDS128(A00[ks], a0base + ks * 512u);
        LDS128(A01[ks], a0base + 2048u + ks * 512u);
        LDS128(A10[ks], a1base + ks * 512u);
        LDS128(A11[ks], a1base + 2048u + ks * 512u);
    }

    float best[4];
    int   bidx[4];
#pragma unroll
    for (int s = 0; s < 4; s++) { best[s] = -3.0e38f; bidx[s] = 0; }

    const int barid = 1 + grp;
    const uint32_t hlane = smb + SM_HE2 + (uint32_t)(lane & 3) * 8u;

    for (int st = 0; st < NSTG; st++) {
        if (st < NSTG - 2) { CP_WAIT(1); } else { CP_WAIT(0); }
        BARG(barid);

        const uint32_t sb = st_base + (uint32_t)(st & 1) * SUB_BYTES;
        const uint32_t bpair = sb + (uint32_t)lane * 16u;
        float acc[32];
#pragma unroll
        for (int z = 0; z < 32; z++) acc[z] = 0.f;

        STEP(0);
        STEP(1);
        STEP(2);
        STEP(3);

        // ---- epilogue: exact fp32 h-subtract + register argmax ----
        const int tbase = (grp * NSTG + st) * 32;
#pragma unroll
        for (int n = 0; n < 4; n++) {
            int tokb = tbase + n * 8 + (lane & 3) * 2;
            float h0, h1;
            LDS64F(h0, h1, hlane + (uint32_t)(tbase + n * 8) * 4u);
#pragma unroll
            for (int ms = 0; ms < 2; ms++) {
                const float* d = &acc[(ms * 4 + n) * 4];
                float v0 = d[0] - h0;
                float v1 = d[1] - h1;
                float v2 = d[2] - h0;
                float v3 = d[3] - h1;
                int s0 = ms * 2;
                if (v0 > best[s0])     { best[s0] = v0;     bidx[s0] = tokb; }
                if (v1 > best[s0])     { best[s0] = v1;     bidx[s0] = tokb + 1; }
                if (v2 > best[s0 + 1]) { best[s0 + 1] = v2; bidx[s0 + 1] = tokb; }
                if (v3 > best[s0 + 1]) { best[s0 + 1] = v3; bidx[s0 + 1] = tokb + 1; }
            }
        }

        BARG(barid);
        if (st + 2 < NSTG) {
            const char* src = (const char*)&g_B[grp * NSTG + st + 2][0];
            uint32_t dst = st_base + (uint32_t)(st & 1) * SUB_BYTES;
#pragma unroll
            for (int it = 0; it < 4; it++) {
                int off = it * 128 * 16 + gtid * 16;
                CP_ASYNC16(dst + off, src + off);
            }
            CP_COMMIT();
        }
    }

    // ---- merge across the 4 lanes sharing each row ----
#pragma unroll
    for (int s = 0; s < 4; s++) {
#pragma unroll
        for (int off = 1; off <= 2; off <<= 1) {
            float os = __shfl_xor_sync(0xffffffffu, best[s], off);
            int   oi = __shfl_xor_sync(0xffffffffu, bidx[s], off);
            if (os > best[s] || (os == best[s] && oi < bidx[s])) {
                best[s] = os; bidx[s] = oi;
            }
        }
    }

    float* REDS = (float*)(sm + SM_REDS);
    int*   REDI = (int*)(sm + SM_REDI);
    int*   QIDX = (int*)(sm + SM_QIDX);
    if ((lane & 3) == 0) {
#pragma unroll
        for (int s = 0; s < 4; s++) {
            int row = mw * 32 + (s >> 1) * 16 + (lane >> 2) + (s & 1) * 8;
            REDS[row * 2 + grp] = best[s];
            REDI[row * 2 + grp] = bidx[s];
        }
    }
    __syncthreads();

    if (tid < QB) {
        float s0 = REDS[tid * 2], s1 = REDS[tid * 2 + 1];
        int   i0 = REDI[tid * 2], i1 = REDI[tid * 2 + 1];
        int bi = (s1 > s0) ? i1 : i0;   // group0 indices lower; tie -> i0
        QIDX[tid] = bi;
        idxout[(size_t)b * CODES + c0 + tid] = (float)bi;
    }
    __syncthreads();

    // ---- gather x_out ----
#pragma unroll
    for (int it = 0; it < (EMB * QB) / NTHREADS; ++it) {
        int idx = it * NTHREADS + tid;
        int q = idx & (QB - 1);
        int j = idx >> 7;
        xout[(size_t)b * EMB * CODES + (size_t)j * CODES + c0 + q] =
            e[(size_t)QIDX[q] * EMB + j];
    }
}

extern "C" void kernel_launch(void* const* d_in, const int* in_sizes, int n_in,
                              void* d_out, int out_size) {
    const float* x = (const float*)d_in[0];   // [16, 64, 16384]
    const float* e = (const float*)d_in[1];   // [1024, 64]
    int B = in_sizes[0] / (EMB * CODES);

    float* xout   = (float*)d_out;
    float* idxout = xout + (size_t)B * EMB * CODES;

    pre_kernel<<<NSUB, 256>>>(e);

    cudaFuncSetAttribute(vq_kernel, cudaFuncAttributeMaxDynamicSharedMemorySize, SM_TOTAL);
    dim3 grid(CODES / QB, B);
    vq_kernel<<<grid, NTHREADS, SM_TOTAL>>>(x, e, xout, idxout);
}